// round 4
// baseline (speedup 1.0000x reference)
#include <cuda_runtime.h>
#include <math.h>

#define BATCH  2
#define SEQ    384
#define EMB    512
#define NHEADS 8
#define HD     64
#define NBH    16      // BATCH*NHEADS
#define MR     768     // BATCH*SEQ

// Scratch (allocation-free rule: __device__ globals)
__device__ float g_q[NBH * SEQ * HD];   // normalized q-hat, [bh][l][64]
__device__ float g_k[NBH * SEQ * HD];   // normalized k-hat
__device__ float g_v[NBH * SEQ * HD];   // raw v
__device__ float g_ctx[NBH * SEQ * HD]; // attention output

// ---------------------------------------------------------------------------
// GEMM: C = A @ W^T.  M=768, N=512, K=512. Both operands K-major (row-major,
// K contiguous). BM=128, BN=64, BK=16, 256 threads, 8x4 microtile.
// PERM_OUT: scatter output to [bh][l][64] layout (+ optional per-atom
//           quaternion normalization fused in epilogue).
// PERM_A:   gather A from g_ctx in [bh][l][64] layout.
// For QKV: launched with gridDim.z = 3; z selects W / destination / norm.
// ---------------------------------------------------------------------------
template <bool PERM_A, bool PERM_OUT>
__global__ __launch_bounds__(256)
void gemm_nt(const float* __restrict__ A,
             const float* __restrict__ W0,
             const float* __restrict__ W1,
             const float* __restrict__ W2,
             float* __restrict__ Cext)
{
    __shared__ float As[16][132];  // [k][m], padded
    __shared__ float Bs[16][68];   // [k][n], padded

    const int tid = threadIdx.x;
    const int tx  = tid & 15;      // n microtile index (4 cols each)
    const int ty  = tid >> 4;      // m microtile index (8 rows each)
    const int m0  = blockIdx.y * 128;
    const int n0  = blockIdx.x * 64;
    const int sel = blockIdx.z;    // 0/1/2 for QKV, 0 for O-proj

    const float* W = (sel == 0) ? W0 : (sel == 1) ? W1 : W2;

    float acc[8][4];
#pragma unroll
    for (int i = 0; i < 8; i++)
#pragma unroll
        for (int j = 0; j < 4; j++) acc[i][j] = 0.0f;

    const int ar = tid >> 1;        // 0..127  A row within tile
    const int ak = (tid & 1) * 8;   // 0 or 8  A k-offset (8 floats)
    const int br = tid >> 2;        // 0..63   B row within tile
    const int bk = (tid & 3) * 4;   // 0..12   B k-offset (4 floats)

    for (int k0 = 0; k0 < EMB; k0 += 16) {
        const float* ap;
        {
            const int m = m0 + ar;
            if (PERM_A) {
                const int b = m / SEQ, l = m - b * SEQ;
                const int e = k0 + ak;        // multiple of 8, stays in head
                const int h = e >> 6, d = e & 63;
                ap = g_ctx + (((b * NHEADS + h) * SEQ + l) * HD + d);
            } else {
                ap = A + m * EMB + k0 + ak;
            }
        }
        const float4 a0 = *(const float4*)ap;
        const float4 a1 = *(const float4*)(ap + 4);
        As[ak + 0][ar] = a0.x; As[ak + 1][ar] = a0.y;
        As[ak + 2][ar] = a0.z; As[ak + 3][ar] = a0.w;
        As[ak + 4][ar] = a1.x; As[ak + 5][ar] = a1.y;
        As[ak + 6][ar] = a1.z; As[ak + 7][ar] = a1.w;

        const float4 bv = *(const float4*)(W + (n0 + br) * EMB + k0 + bk);
        Bs[bk + 0][br] = bv.x; Bs[bk + 1][br] = bv.y;
        Bs[bk + 2][br] = bv.z; Bs[bk + 3][br] = bv.w;

        __syncthreads();
#pragma unroll
        for (int kk = 0; kk < 16; kk++) {
            const float4 a0v = *(const float4*)&As[kk][ty * 8];
            const float4 a1v = *(const float4*)&As[kk][ty * 8 + 4];
            const float4 b4  = *(const float4*)&Bs[kk][tx * 4];
            const float am[8] = {a0v.x, a0v.y, a0v.z, a0v.w,
                                 a1v.x, a1v.y, a1v.z, a1v.w};
            const float bn[4] = {b4.x, b4.y, b4.z, b4.w};
#pragma unroll
            for (int i = 0; i < 8; i++)
#pragma unroll
                for (int j = 0; j < 4; j++)
                    acc[i][j] = fmaf(am[i], bn[j], acc[i][j]);
        }
        __syncthreads();
    }

    float* C = Cext;
    bool do_norm = false;
    if (PERM_OUT) {
        C = (sel == 0) ? g_q : (sel == 1) ? g_k : g_v;
        do_norm = (sel < 2);  // normalize q and k, not v
    }

#pragma unroll
    for (int i = 0; i < 8; i++) {
        const int m = m0 + ty * 8 + i;
        const int f = n0 + tx * 4;   // 4 consecutive cols == one atom
        float4 r = make_float4(acc[i][0], acc[i][1], acc[i][2], acc[i][3]);
        if (do_norm) {
            const float d2 = r.x * r.x + r.y * r.y + r.z * r.z + r.w * r.w;
            const float inv = __fdividef(1.0f, sqrtf(d2) + 1e-12f);
            r.x *= inv; r.y *= inv; r.z *= inv; r.w *= inv;
        }
        if (PERM_OUT) {
            const int b = m / SEQ, l = m - b * SEQ;
            const int h = f >> 6, d = f & 63;
            *(float4*)(C + (((b * NHEADS + h) * SEQ + l) * HD + d)) = r;
        } else {
            *(float4*)(C + m * EMB + f) = r;
        }
    }
}

// ---------------------------------------------------------------------------
// Attention core
// ---------------------------------------------------------------------------
__device__ __forceinline__ float4 qmul(const float4 a, const float4 b)
{
    // components: .x=w .y=x .z=y .w=z
    float4 r;
    r.x = fmaf(a.x, b.x, fmaf(-a.y, b.y, fmaf(-a.z, b.z, -a.w * b.w)));
    r.y = fmaf(a.x, b.y, fmaf( a.y, b.x, fmaf( a.z, b.w, -a.w * b.z)));
    r.z = fmaf(a.x, b.z, fmaf(-a.y, b.w, fmaf( a.z, b.x,  a.w * b.y)));
    r.w = fmaf(a.x, b.w, fmaf( a.y, b.z, fmaf(-a.z, b.y,  a.w * b.x)));
    return r;
}

__device__ __forceinline__ void qmul_acc(float4& c, const float4 a, const float4 b)
{
    c.x = fmaf(a.x, b.x, fmaf(-a.y, b.y, fmaf(-a.z, b.z, fmaf(-a.w, b.w, c.x))));
    c.y = fmaf(a.x, b.y, fmaf( a.y, b.x, fmaf( a.z, b.w, fmaf(-a.w, b.z, c.y))));
    c.z = fmaf(a.x, b.z, fmaf(-a.y, b.w, fmaf( a.z, b.x, fmaf( a.w, b.y, c.z))));
    c.w = fmaf(a.x, b.w, fmaf( a.y, b.z, fmaf(-a.z, b.y, fmaf( a.w, b.x, c.w))));
}

__device__ __forceinline__ float sigm(float x)
{
    return __fdividef(1.0f, 1.0f + __expf(-x));
}

#define TJ 64  // j-tile staged in smem

__global__ __launch_bounds__(128)
void attn_core(const float* __restrict__ dde_w, const float* __restrict__ dde_b)
{
    __shared__ float4 ks4[TJ * 16];  // 16KB : k-hat tile [j][atom]
    __shared__ float4 vs4[TJ * 16];  // 16KB : v tile

    const int tid  = threadIdx.x;
    const int lane = tid & 7;                      // handles atoms lane, lane+8
    const int row  = blockIdx.x * 16 + (tid >> 3); // query index i
    const int bh   = blockIdx.y;

    // gate weights, 1/16 (atom mean) pre-folded
    float w16[4][4], bb[4];
#pragma unroll
    for (int p = 0; p < 4; p++) {
        bb[p] = dde_b[p];
#pragma unroll
        for (int q = 0; q < 4; q++) w16[p][q] = dde_w[p * 4 + q] * 0.0625f;
    }

    const float* qp = g_q + (bh * SEQ + row) * HD;
    const float4 qA = *(const float4*)(qp + lane * 4);
    const float4 qB = *(const float4*)(qp + (lane + 8) * 4);
    float4 cA = make_float4(0.f, 0.f, 0.f, 0.f);
    float4 cB = make_float4(0.f, 0.f, 0.f, 0.f);

    for (int j0 = 0; j0 < SEQ; j0 += TJ) {
        const float4* kg = (const float4*)(g_k + (bh * SEQ + j0) * HD);
        const float4* vg = (const float4*)(g_v + (bh * SEQ + j0) * HD);
#pragma unroll
        for (int t = 0; t < (TJ * 16) / 128; t++) {  // 8 float4s per thread each
            ks4[tid + t * 128] = kg[tid + t * 128];
            vs4[tid + t * 128] = vg[tid + t * 128];
        }
        __syncthreads();

#pragma unroll 4
        for (int j = 0; j < TJ; j++) {
            const float4 kA = ks4[j * 16 + lane];
            const float4 kB = ks4[j * 16 + lane + 8];
            const float4 sA = qmul(qA, kA);     // unit spinor, atom lane
            const float4 sB = qmul(qB, kB);     // unit spinor, atom lane+8

            // sum of spinor over all 16 atoms (pairs + 8-lane butterfly)
            float s0 = sA.x + sB.x, s1 = sA.y + sB.y;
            float s2 = sA.z + sB.z, s3 = sA.w + sB.w;
#pragma unroll
            for (int off = 1; off < 8; off <<= 1) {
                s0 += __shfl_xor_sync(0xffffffffu, s0, off);
                s1 += __shfl_xor_sync(0xffffffffu, s1, off);
                s2 += __shfl_xor_sync(0xffffffffu, s2, off);
                s3 += __shfl_xor_sync(0xffffffffu, s3, off);
            }

            const float g0 = sigm(fmaf(s0, w16[0][0], fmaf(s1, w16[0][1], fmaf(s2, w16[0][2], fmaf(s3, w16[0][3], bb[0])))));
            const float g1 = sigm(fmaf(s0, w16[1][0], fmaf(s1, w16[1][1], fmaf(s2, w16[1][2], fmaf(s3, w16[1][3], bb[1])))));
            const float g2 = sigm(fmaf(s0, w16[2][0], fmaf(s1, w16[2][1], fmaf(s2, w16[2][2], fmaf(s3, w16[2][3], bb[2])))));
            const float g3 = sigm(fmaf(s0, w16[3][0], fmaf(s1, w16[3][1], fmaf(s2, w16[3][2], fmaf(s3, w16[3][3], bb[3])))));

            const float4 vA = vs4[j * 16 + lane];
            const float4 vB = vs4[j * 16 + lane + 8];
            const float4 gA = make_float4(sA.x * g0, sA.y * g1, sA.z * g2, sA.w * g3);
            const float4 gB = make_float4(sB.x * g0, sB.y * g1, sB.z * g2, sB.w * g3);
            qmul_acc(cA, gA, vA);
            qmul_acc(cB, gB, vB);
        }
        __syncthreads();
    }

    float* cp = g_ctx + (bh * SEQ + row) * HD;
    *(float4*)(cp + lane * 4)       = cA;
    *(float4*)(cp + (lane + 8) * 4) = cB;
}

// ---------------------------------------------------------------------------
extern "C" void kernel_launch(void* const* d_in, const int* in_sizes, int n_in,
                              void* d_out, int out_size)
{
    (void)in_sizes; (void)n_in; (void)out_size;
    const float* x  = (const float*)d_in[0];
    const float* Wq = (const float*)d_in[1];
    const float* Wk = (const float*)d_in[2];
    const float* Wv = (const float*)d_in[3];
    const float* Wo = (const float*)d_in[4];
    const float* dw = (const float*)d_in[5];
    const float* db = (const float*)d_in[6];
    float* out = (float*)d_out;

    // QKV projections (fused over grid.z), normalization fused in epilogue
    dim3 gqkv(EMB / 64, MR / 128, 3);   // (8, 6, 3) = 144 blocks
    gemm_nt<false, true><<<gqkv, 256>>>(x, Wq, Wk, Wv, nullptr);

    // Pairwise quaternion attention core
    attn_core<<<dim3(SEQ / 16, NBH), 128>>>(dw, db);

    // Output projection
    dim3 go(EMB / 64, MR / 128, 1);     // (8, 6) = 48 blocks
    gemm_nt<true, false><<<go, 256>>>(nullptr, Wo, Wo, Wo, out);
}